// round 6
// baseline (speedup 1.0000x reference)
#include <cuda_runtime.h>
#include <float.h>

// Problem constants
#define DIMS      256      // embedding dim
#define KCODES    1024     // num embeddings
#define HWSZ      1024     // H*W = 32*32
#define BATCH     32
#define NROWS     32768    // BATCH * HWSZ
#define NUMEL     8388608  // BATCH * DIMS * HWSZ

// Tiling
#define TM        64       // rows per CTA
#define TK        128      // codes per k-tile
#define TD        16       // d-chunk per pipeline step
#define NTHREADS  256
#define WS_STRIDE 132      // TK + 4 pad (2-way instead of 16-way STS conflicts)
#define NTILES    128      // (KCODES/TK) * (DIMS/TD) = 8 * 16

__device__ float g_wsq[KCODES];
__device__ float g_loss;

// ---- packed fp32x2 helpers (FFMA2: 2 exact IEEE fp32 FMAs per instruction) ----
__device__ __forceinline__ unsigned long long pk2(float lo, float hi) {
    unsigned long long r;
    asm("mov.b64 %0, {%1, %2};" : "=l"(r) : "f"(lo), "f"(hi));
    return r;
}
__device__ __forceinline__ void upk2(unsigned long long v, float& lo, float& hi) {
    asm("mov.b64 {%0, %1}, %2;" : "=f"(lo), "=f"(hi) : "l"(v));
}
__device__ __forceinline__ void ffma2(unsigned long long& d,
                                      unsigned long long a,
                                      unsigned long long b) {
    asm("fma.rn.f32x2 %0, %1, %2, %0;" : "+l"(d) : "l"(a), "l"(b));
}

// ---------------------------------------------------------------------------
// Kernel 1: ||w_k||^2 per code (one warp per code), and zero the loss accum.
// ---------------------------------------------------------------------------
__global__ void vq_wsq_kernel(const float* __restrict__ w) {
    if (blockIdx.x == 0 && threadIdx.x == 0) g_loss = 0.0f;
    int warp = threadIdx.x >> 5;
    int lane = threadIdx.x & 31;
    int k = blockIdx.x * 8 + warp;       // 256 threads = 8 warps per block
    if (k >= KCODES) return;
    const float* row = w + (size_t)k * DIMS;
    float s = 0.0f;
    #pragma unroll
    for (int j = 0; j < DIMS / 32; j++) {
        float v = row[lane + j * 32];
        s += v * v;
    }
    #pragma unroll
    for (int off = 16; off > 0; off >>= 1)
        s += __shfl_xor_sync(0xFFFFFFFFu, s, off);
    if (lane == 0) g_wsq[k] = s;
}

// ---------------------------------------------------------------------------
// Kernel 2: fused distance-GEMM + argmin + codebook gather + loss + output.
// Inner product via packed fma.rn.f32x2 (bit-identical to scalar fmaf chain,
// half the FMA-class instructions -> ~2x fma-pipe throughput).
// ---------------------------------------------------------------------------
__global__ void __launch_bounds__(NTHREADS)
vq_main_kernel(const float* __restrict__ x,   // [B, D, HW] (NCHW)
               const float* __restrict__ w,   // [K, D]
               float* __restrict__ out)       // [B, D, HW]
{
    __shared__ __align__(16) float As[2][TD][TM];          // 8 KB
    __shared__ __align__(16) float Ws[2][TD][WS_STRIDE];   // 16.5 KB
    __shared__ float wsq_s[KCODES];                        // 4 KB
    __shared__ int   sidx[TM];

    const int tid = threadIdx.x;
    const int tx  = tid & 15;    // code-dim thread coord (8 codes each)
    const int ty  = tid >> 4;    // row-dim thread coord (4 rows each)

    const int tile = blockIdx.x;         // 0..511
    const int b    = tile >> 4;
    const int hw0  = (tile & 15) * TM;
    const float* xb = x + (size_t)b * DIMS * HWSZ + hw0;

    // wsq -> smem (needed for every epilogue)
    #pragma unroll
    for (int i = tid; i < KCODES; i += NTHREADS) wsq_s[i] = g_wsq[i];

    // per-thread running argmin for its 4 rows
    float bestv[4] = {FLT_MAX, FLT_MAX, FLT_MAX, FLT_MAX};
    int   besti[4] = {0, 0, 0, 0};

    // ---- software pipeline: global -> regs -> smem, double buffered ----
    const int a_dd0 = tid >> 6;      // loadA: dd = a_dd0 + j*4, m = a_m
    const int a_m   = tid & 63;
    const int w_dd  = tid & 15;      // loadW: kk = w_kk0 + j*16
    const int w_kk0 = tid >> 4;

    float ra[4], rw[8];

    // preload tile 0 (kt=0, ds=0)
    #pragma unroll
    for (int j = 0; j < 4; j++)
        ra[j] = xb[(a_dd0 + j * 4) * HWSZ + a_m];
    {
        const float* wb = w;  // kt=0, ds=0
        #pragma unroll
        for (int j = 0; j < 8; j++)
            rw[j] = wb[(w_kk0 + j * 16) * DIMS + w_dd];
    }
    #pragma unroll
    for (int j = 0; j < 4; j++) As[0][a_dd0 + j * 4][a_m] = ra[j];
    #pragma unroll
    for (int j = 0; j < 8; j++) Ws[0][w_dd][w_kk0 + j * 16] = rw[j];
    __syncthreads();

    int buf = 0;
    #pragma unroll 1
    for (int kt = 0; kt < KCODES / TK; kt++) {
        // packed accumulators: acc2[mi][kj] holds codes (2*kj, 2*kj+1)
        unsigned long long acc2[4][4];
        #pragma unroll
        for (int mi = 0; mi < 4; mi++)
            #pragma unroll
            for (int kj = 0; kj < 4; kj++) acc2[mi][kj] = 0ULL;

        #pragma unroll 1
        for (int ds = 0; ds < DIMS / TD; ds++) {
            const int t  = kt * 16 + ds;
            const int nt = t + 1;
            if (nt < NTILES) {
                const int nkt = nt >> 4, nds = nt & 15;
                #pragma unroll
                for (int j = 0; j < 4; j++)
                    ra[j] = xb[(nds * TD + a_dd0 + j * 4) * HWSZ + a_m];
                const float* wb = w + (size_t)(nkt * TK) * DIMS + nds * TD;
                #pragma unroll
                for (int j = 0; j < 8; j++)
                    rw[j] = wb[(w_kk0 + j * 16) * DIMS + w_dd];
            }

            // compute on current buffer: 16 d-steps x (4 rows x 4 code-pairs)
            #pragma unroll
            for (int dd = 0; dd < TD; dd++) {
                float4 av = *(const float4*)&As[buf][dd][ty * 4];
                float4 b0 = *(const float4*)&Ws[buf][dd][tx * 8];
                float4 b1 = *(const float4*)&Ws[buf][dd][tx * 8 + 4];
                unsigned long long bb[4] = {
                    pk2(b0.x, b0.y), pk2(b0.z, b0.w),
                    pk2(b1.x, b1.y), pk2(b1.z, b1.w)
                };
                unsigned long long aa[4] = {
                    pk2(av.x, av.x), pk2(av.y, av.y),
                    pk2(av.z, av.z), pk2(av.w, av.w)
                };
                #pragma unroll
                for (int mi = 0; mi < 4; mi++)
                    #pragma unroll
                    for (int kj = 0; kj < 4; kj++)
                        ffma2(acc2[mi][kj], aa[mi], bb[kj]);
            }

            if (nt < NTILES) {
                const int nb = buf ^ 1;
                #pragma unroll
                for (int j = 0; j < 4; j++) As[nb][a_dd0 + j * 4][a_m] = ra[j];
                #pragma unroll
                for (int j = 0; j < 8; j++) Ws[nb][w_dd][w_kk0 + j * 16] = rw[j];
            }
            __syncthreads();
            buf ^= 1;
        }

        // epilogue for this k-tile: dist = ||w||^2 - 2*dot ; running argmin
        const int kb = kt * TK + tx * 8;
        #pragma unroll
        for (int mi = 0; mi < 4; mi++) {
            #pragma unroll
            for (int kj = 0; kj < 4; kj++) {
                float d0, d1;
                upk2(acc2[mi][kj], d0, d1);
                int i0 = kb + 2 * kj, i1 = i0 + 1;
                float dist0 = wsq_s[i0] - 2.0f * d0;
                float dist1 = wsq_s[i1] - 2.0f * d1;
                // ascending scan: strict < keeps earliest; == tie -> lower idx
                if (dist0 < bestv[mi] ||
                    (dist0 == bestv[mi] && i0 < besti[mi])) {
                    bestv[mi] = dist0; besti[mi] = i0;
                }
                if (dist1 < bestv[mi] ||
                    (dist1 == bestv[mi] && i1 < besti[mi])) {
                    bestv[mi] = dist1; besti[mi] = i1;
                }
            }
        }
    }

    // ---- cross-thread argmin reduction (16 tx threads per row) ----
    __syncthreads();
    float* redv = (float*)Ws;            // reuse Ws as scratch (done with it)
    int*   redi = (int*)((float*)Ws + TM * 16);
    #pragma unroll
    for (int mi = 0; mi < 4; mi++) {
        int m = ty * 4 + mi;
        redv[m * 16 + tx] = bestv[mi];
        redi[m * 16 + tx] = besti[mi];
    }
    __syncthreads();
    if (tid < TM) {
        float bv = FLT_MAX; int bi = 0x7FFFFFFF;
        #pragma unroll
        for (int j = 0; j < 16; j++) {
            float v = redv[tid * 16 + j];
            int   i = redi[tid * 16 + j];
            if (v < bv || (v == bv && i < bi)) { bv = v; bi = i; }
        }
        sidx[tid] = bi;
    }
    __syncthreads();

    // ---- gather codebook rows, write NCHW output, accumulate loss ----
    float* outb = out + (size_t)b * DIMS * HWSZ + hw0;
    float lsum = 0.0f;
    #pragma unroll 1
    for (int i = tid; i < TM * (DIMS / 4); i += NTHREADS) {
        int m  = i & 63;          // lanes -> consecutive m: coalesced x/out
        int dc = i >> 6;
        float4 q = *(const float4*)&w[(size_t)sidx[m] * DIMS + dc * 4];
        float qv[4] = {q.x, q.y, q.z, q.w};
        #pragma unroll
        for (int j = 0; j < 4; j++) {
            int d = dc * 4 + j;
            float xv = xb[d * HWSZ + m];
            float df = qv[j] - xv;
            lsum = fmaf(df, df, lsum);
            outb[d * HWSZ + m] = qv[j];
        }
    }

    // block-reduce loss, one atomic per CTA
    #pragma unroll
    for (int off = 16; off > 0; off >>= 1)
        lsum += __shfl_xor_sync(0xFFFFFFFFu, lsum, off);
    __syncthreads();
    float* lred = (float*)Ws;
    if ((tid & 31) == 0) lred[tid >> 5] = lsum;
    __syncthreads();
    if (tid == 0) {
        float s = 0.0f;
        #pragma unroll
        for (int j = 0; j < NTHREADS / 32; j++) s += lred[j];
        atomicAdd(&g_loss, s);
    }
}

// ---------------------------------------------------------------------------
// Kernel 3: finalize loss scalar -> tail of output buffer.
// loss = codebook_loss + 0.25*commit_loss = 1.25 * mean((q-x)^2)
// ---------------------------------------------------------------------------
__global__ void vq_finalize_kernel(float* __restrict__ out, int out_size) {
    if (out_size > NUMEL)
        out[NUMEL] = g_loss * (1.25f / (float)NUMEL);
}

// ---------------------------------------------------------------------------
extern "C" void kernel_launch(void* const* d_in, const int* in_sizes, int n_in,
                              void* d_out, int out_size) {
    const float* x = (const float*)d_in[0];   // [32, 256, 32, 32] fp32
    const float* w = (const float*)d_in[1];   // [1024, 256] fp32
    float* out = (float*)d_out;

    vq_wsq_kernel<<<KCODES / 8, 256>>>(w);
    vq_main_kernel<<<NROWS / TM, NTHREADS>>>(x, w, out);
    vq_finalize_kernel<<<1, 1>>>(out, out_size);
}

// round 10
// speedup vs baseline: 1.6639x; 1.6639x over previous
#include <cuda_runtime.h>
#include <float.h>

// Problem constants
#define DIMS      256      // embedding dim
#define KCODES    1024     // num embeddings
#define HWSZ      1024     // H*W = 32*32
#define BATCH     32
#define NROWS     32768    // BATCH * HWSZ
#define NUMEL     8388608  // BATCH * DIMS * HWSZ

// Tiling
#define TM        128      // rows per CTA
#define TK        128      // codes per k-tile
#define TD        16       // d-chunk per pipeline step
#define NTHREADS  256
#define WS_STRIDE 132      // TK + 4 pad
#define NTILES    128      // (KCODES/TK) * (DIMS/TD) = 8 * 16

__device__ float g_wsq[KCODES];
__device__ float g_loss;

typedef unsigned long long u64t;

// ---- packed fp32x2 helpers (FFMA2: 2 exact IEEE fp32 FMAs per instruction) ----
__device__ __forceinline__ u64t pk2(float lo, float hi) {
    u64t r;
    asm("mov.b64 %0, {%1, %2};" : "=l"(r) : "f"(lo), "f"(hi));
    return r;
}
__device__ __forceinline__ void upk2(u64t v, float& lo, float& hi) {
    asm("mov.b64 {%0, %1}, %2;" : "=f"(lo), "=f"(hi) : "l"(v));
}
__device__ __forceinline__ void ffma2(u64t& d, u64t a, u64t b) {
    asm("fma.rn.f32x2 %0, %1, %2, %0;" : "+l"(d) : "l"(a), "l"(b));
}

// ---------------------------------------------------------------------------
// Kernel 1: ||w_k||^2 per code (one warp per code), and zero the loss accum.
// ---------------------------------------------------------------------------
__global__ void vq_wsq_kernel(const float* __restrict__ w) {
    if (blockIdx.x == 0 && threadIdx.x == 0) g_loss = 0.0f;
    int warp = threadIdx.x >> 5;
    int lane = threadIdx.x & 31;
    int k = blockIdx.x * 8 + warp;
    if (k >= KCODES) return;
    const float* row = w + (size_t)k * DIMS;
    float s = 0.0f;
    #pragma unroll
    for (int j = 0; j < DIMS / 32; j++) {
        float v = row[lane + j * 32];
        s += v * v;
    }
    #pragma unroll
    for (int off = 16; off > 0; off >>= 1)
        s += __shfl_xor_sync(0xFFFFFFFFu, s, off);
    if (lane == 0) g_wsq[k] = s;
}

// ---------------------------------------------------------------------------
// Kernel 2: fused distance-GEMM + argmin + gather + loss + output.
// TM=128: 4x larger compute window per stage hides 234-262cyc L2 prefetch
// latency (the Round-6 bound).  8x8 per-thread tile, accumulators packed
// pairwise along M (fma.rn.f32x2, exact IEEE fp32 per lane).
// ---------------------------------------------------------------------------
__global__ void __launch_bounds__(NTHREADS)
vq_main_kernel(const float* __restrict__ x,   // [B, D, HW] (NCHW)
               const float* __restrict__ w,   // [K, D]
               float* __restrict__ out)       // [B, D, HW]
{
    __shared__ __align__(16) float As[2][TD][TM];          // 16 KB
    __shared__ __align__(16) float Ws[2][TD][WS_STRIDE];   // 16.9 KB
    __shared__ float wsq_s[KCODES];                        // 4 KB
    __shared__ int   sidx[TM];

    const int tid = threadIdx.x;
    const int tx  = tid & 15;    // code coord: 8 codes  (tx*8 + kj)
    const int ty  = tid >> 4;    // row  coord: 8 rows   (ty*8 + r)

    const int tile = blockIdx.x;         // 0..255
    const int b    = tile >> 3;
    const int hw0  = (tile & 7) * TM;
    const float* xb = x + (size_t)b * DIMS * HWSZ + hw0;

    #pragma unroll
    for (int i = tid; i < KCODES; i += NTHREADS) wsq_s[i] = g_wsq[i];

    float bestv[8];
    int   besti[8];
    #pragma unroll
    for (int r = 0; r < 8; r++) { bestv[r] = FLT_MAX; besti[r] = 0; }

    // ---- global->reg->smem double-buffered pipeline ----
    // A: 2 x LDG.128 per thread per stage (coalesced along hw)
    const int a_dd0 = tid >> 5;          // 0..7 ; dd = a_dd0 + j*8
    const int a_m4  = (tid & 31) * 4;    // 0..124
    // W: 8 x LDG.32 per thread per stage
    const int w_dd  = tid & 15;
    const int w_kk0 = tid >> 4;

    float4 ra[2];
    float  rw[8];

    // preload tile 0 (kt=0, ds=0)
    #pragma unroll
    for (int j = 0; j < 2; j++)
        ra[j] = *(const float4*)&xb[(size_t)(a_dd0 + j * 8) * HWSZ + a_m4];
    #pragma unroll
    for (int j = 0; j < 8; j++)
        rw[j] = w[(size_t)(w_kk0 + j * 16) * DIMS + w_dd];
    #pragma unroll
    for (int j = 0; j < 2; j++)
        *(float4*)&As[0][a_dd0 + j * 8][a_m4] = ra[j];
    #pragma unroll
    for (int j = 0; j < 8; j++)
        Ws[0][w_dd][w_kk0 + j * 16] = rw[j];
    __syncthreads();

    int buf = 0;
    #pragma unroll 1
    for (int kt = 0; kt < KCODES / TK; kt++) {
        // acc2[rp][kj]: rows (ty*8+2rp, ty*8+2rp+1) x code (tx*8+kj)
        u64t acc2[4][8];
        #pragma unroll
        for (int rp = 0; rp < 4; rp++)
            #pragma unroll
            for (int kj = 0; kj < 8; kj++) acc2[rp][kj] = 0ULL;

        #pragma unroll 1
        for (int ds = 0; ds < DIMS / TD; ds++) {
            const int nt = kt * 16 + ds + 1;
            if (nt < NTILES) {
                const int nkt = nt >> 4, nds = nt & 15;
                #pragma unroll
                for (int j = 0; j < 2; j++)
                    ra[j] = *(const float4*)
                        &xb[(size_t)(nds * TD + a_dd0 + j * 8) * HWSZ + a_m4];
                const float* wb = w + (size_t)(nkt * TK) * DIMS + nds * TD;
                #pragma unroll
                for (int j = 0; j < 8; j++)
                    rw[j] = wb[(size_t)(w_kk0 + j * 16) * DIMS + w_dd];
            }

            // 16 d-steps x (4 row-pairs x 8 codes) FFMA2
            #pragma unroll
            for (int dd = 0; dd < TD; dd++) {
                float4 av0 = *(const float4*)&As[buf][dd][ty * 8];
                float4 av1 = *(const float4*)&As[buf][dd][ty * 8 + 4];
                float4 b0  = *(const float4*)&Ws[buf][dd][tx * 8];
                float4 b1  = *(const float4*)&Ws[buf][dd][tx * 8 + 4];
                u64t aa[4] = {
                    pk2(av0.x, av0.y), pk2(av0.z, av0.w),
                    pk2(av1.x, av1.y), pk2(av1.z, av1.w)
                };
                u64t bb[8] = {
                    pk2(b0.x, b0.x), pk2(b0.y, b0.y),
                    pk2(b0.z, b0.z), pk2(b0.w, b0.w),
                    pk2(b1.x, b1.x), pk2(b1.y, b1.y),
                    pk2(b1.z, b1.z), pk2(b1.w, b1.w)
                };
                #pragma unroll
                for (int rp = 0; rp < 4; rp++)
                    #pragma unroll
                    for (int kj = 0; kj < 8; kj++)
                        ffma2(acc2[rp][kj], aa[rp], bb[kj]);
            }

            if (nt < NTILES) {
                const int nb = buf ^ 1;
                #pragma unroll
                for (int j = 0; j < 2; j++)
                    *(float4*)&As[nb][a_dd0 + j * 8][a_m4] = ra[j];
                #pragma unroll
                for (int j = 0; j < 8; j++)
                    Ws[nb][w_dd][w_kk0 + j * 16] = rw[j];
            }
            __syncthreads();
            buf ^= 1;
        }

        // epilogue: dist = ||w||^2 - 2*dot ; running argmin per row
        const int kb = kt * TK + tx * 8;
        #pragma unroll
        for (int rp = 0; rp < 4; rp++) {
            #pragma unroll
            for (int kj = 0; kj < 8; kj++) {
                float d0, d1;
                upk2(acc2[rp][kj], d0, d1);       // rows 2rp, 2rp+1
                const int idx = kb + kj;
                const float wq = wsq_s[idx];
                float dist0 = wq - 2.0f * d0;
                float dist1 = wq - 2.0f * d1;
                const int r0 = 2 * rp, r1 = 2 * rp + 1;
                // ascending code scan: strict < keeps earliest index
                if (dist0 < bestv[r0] ||
                    (dist0 == bestv[r0] && idx < besti[r0])) {
                    bestv[r0] = dist0; besti[r0] = idx;
                }
                if (dist1 < bestv[r1] ||
                    (dist1 == bestv[r1] && idx < besti[r1])) {
                    bestv[r1] = dist1; besti[r1] = idx;
                }
            }
        }
    }

    // ---- cross-thread argmin reduction (16 tx threads per row) ----
    __syncthreads();
    float* redv = (float*)As;            // 128*16 floats = 8KB (As is 16KB)
    int*   redi = (int*)Ws;              // 128*16 ints   = 8KB (Ws is 16.9KB)
    #pragma unroll
    for (int r = 0; r < 8; r++) {
        int m = ty * 8 + r;
        redv[m * 16 + tx] = bestv[r];
        redi[m * 16 + tx] = besti[r];
    }
    __syncthreads();
    if (tid < TM) {
        float bv = FLT_MAX; int bi = 0x7FFFFFFF;
        #pragma unroll
        for (int j = 0; j < 16; j++) {
            float v = redv[tid * 16 + j];
            int   i = redi[tid * 16 + j];
            if (v < bv || (v == bv && i < bi)) { bv = v; bi = i; }
        }
        sidx[tid] = bi;
    }
    __syncthreads();

    // ---- gather codebook rows, write NCHW output, accumulate loss ----
    float* outb = out + (size_t)b * DIMS * HWSZ + hw0;
    float lsum = 0.0f;
    #pragma unroll 1
    for (int i = tid; i < TM * (DIMS / 4); i += NTHREADS) {
        int m  = i & (TM - 1);    // lanes -> consecutive m: coalesced x/out
        int dc = i >> 7;
        float4 q = *(const float4*)&w[(size_t)sidx[m] * DIMS + dc * 4];
        float qv[4] = {q.x, q.y, q.z, q.w};
        #pragma unroll
        for (int j = 0; j < 4; j++) {
            int d = dc * 4 + j;
            float xv = xb[(size_t)d * HWSZ + m];
            float df = qv[j] - xv;
            lsum = fmaf(df, df, lsum);
            outb[(size_t)d * HWSZ + m] = qv[j];
        }
    }

    // block-reduce loss, one atomic per CTA
    #pragma unroll
    for (int off = 16; off > 0; off >>= 1)
        lsum += __shfl_xor_sync(0xFFFFFFFFu, lsum, off);
    __syncthreads();
    float* lred = (float*)As;
    if ((tid & 31) == 0) lred[tid >> 5] = lsum;
    __syncthreads();
    if (tid == 0) {
        float s = 0.0f;
        #pragma unroll
        for (int j = 0; j < NTHREADS / 32; j++) s += lred[j];
        atomicAdd(&g_loss, s);
    }
}

// ---------------------------------------------------------------------------
// Kernel 3: finalize loss scalar -> tail of output buffer.
// loss = codebook_loss + 0.25*commit_loss = 1.25 * mean((q-x)^2)
// ---------------------------------------------------------------------------
__global__ void vq_finalize_kernel(float* __restrict__ out, int out_size) {
    if (out_size > NUMEL)
        out[NUMEL] = g_loss * (1.25f / (float)NUMEL);
}

// ---------------------------------------------------------------------------
extern "C" void kernel_launch(void* const* d_in, const int* in_sizes, int n_in,
                              void* d_out, int out_size) {
    const float* x = (const float*)d_in[0];   // [32, 256, 32, 32] fp32
    const float* w = (const float*)d_in[1];   // [1024, 256] fp32
    float* out = (float*)d_out;

    vq_wsq_kernel<<<KCODES / 8, 256>>>(w);
    vq_main_kernel<<<NROWS / TM, NTHREADS>>>(x, w, out);
    vq_finalize_kernel<<<1, 1>>>(out, out_size);
}